// round 14
// baseline (speedup 1.0000x reference)
#include <cuda_runtime.h>
#include <cuda_bf16.h>
#include <cuda_fp8.h>
#include <cfloat>
#include <cstdint>

// ---------------------------------------------------------------------------
// Problem constants
// ---------------------------------------------------------------------------
#define NTEST   16384
#define NTRAIN  16384
#define DIM     192
#define NCLASS  2
#define KNN     5

#define TM      128                 // test rows per CTA
#define TN      128                 // train cols per tile
#define NTILES  (NTRAIN / TN)       // 128
#define KSTEPS  (DIM / 32)          // 6 mma k-steps (fp8: K=32 per step)
#define NTHREADS 512                // 16 warps: 4 (M) x 4 (N), warp tile 32x32
#define NSLOT   5                   // private top-5 per (thread,row-slot)
#define NOWN    16                  // owners per row
#define NDUMP   (NOWN * NSLOT)      // 80 candidates dumped per row
#define NCAND   16                  // compacted top-16 per row for re-rank

#define RSB     208                 // bytes per fp8 row in smem (192 + 16 pad)
#define TILEB   (TN * RSB)          // 26624 bytes per B tile

// ---------------------------------------------------------------------------
// Global scratch (no cudaMalloc allowed)
// ---------------------------------------------------------------------------
__device__ float   g_ynorm[NTRAIN];
__device__ uint8_t g_A8[NTEST * DIM];            // H_test  e4m3, row-major 192B rows
__device__ uint8_t g_B8[NTILES * TILEB];         // H_train e4m3, tile-padded layout

// ---------------------------------------------------------------------------
// PTX helpers (base ISA: sm_89/sm_90 features, legal on sm_100 without 'a')
// ---------------------------------------------------------------------------
__device__ __forceinline__ uint32_t smem_u32(const void* p) {
    uint32_t a;
    asm("{ .reg .u64 t; cvta.to.shared.u64 t, %1; cvt.u32.u64 %0, t; }"
        : "=r"(a) : "l"(p));
    return a;
}

#define CP_ASYNC16(dst, src) \
    asm volatile("cp.async.cg.shared.global [%0], [%1], 16;" :: "r"(dst), "l"(src))
#define CP_COMMIT() asm volatile("cp.async.commit_group;" ::: "memory")
#define CP_WAIT0()  asm volatile("cp.async.wait_group 0;" ::: "memory")

#define MBAR_INIT(mb, n) \
    asm volatile("mbarrier.init.shared.b64 [%0], %1;" :: "r"((uint32_t)(mb)), "r"((uint32_t)(n)) : "memory")
#define MBAR_EXPECT_TX(mb, bytes) \
    asm volatile("mbarrier.arrive.expect_tx.shared.b64 _, [%0], %1;" :: "r"((uint32_t)(mb)), "r"((uint32_t)(bytes)) : "memory")
#define CP_BULK(dst, src, sz, mb) \
    asm volatile("cp.async.bulk.shared::cluster.global.mbarrier::complete_tx::bytes [%0], [%1], %2, [%3];" \
                 :: "r"((uint32_t)(dst)), "l"(src), "r"((uint32_t)(sz)), "r"((uint32_t)(mb)) : "memory")
#define FENCE_PROXY_ASYNC() asm volatile("fence.proxy.async.shared::cta;" ::: "memory")

#define MBAR_WAIT(mb, par) do {                                                     \
    uint32_t _mb = (uint32_t)(mb); uint32_t _p = (uint32_t)(par); uint32_t _done;   \
    asm volatile("{ .reg .pred p; mbarrier.try_wait.parity.acquire.cta.shared::cta.b64 p, [%1], %2; selp.b32 %0, 1, 0, p; }" \
                 : "=r"(_done) : "r"(_mb), "r"(_p) : "memory");                     \
    if (!_done) {                                                                   \
        asm volatile("{ .reg .pred P1; WL_%=: mbarrier.try_wait.parity.acquire.cta.shared::cta.b64 P1, [%0], %1, 0x989680; @P1 bra.uni WD_%=; bra.uni WL_%=; WD_%=: }" \
                     :: "r"(_mb), "r"(_p) : "memory");                              \
    }                                                                               \
} while (0)

#define LDMATRIX_X4(r0, r1, r2, r3, addr) \
    asm volatile("ldmatrix.sync.aligned.m8n8.x4.shared.b16 {%0,%1,%2,%3}, [%4];" \
                 : "=r"(r0), "=r"(r1), "=r"(r2), "=r"(r3) : "r"(addr))

__device__ __forceinline__ void mma_fp8(float* c,
                                        uint32_t a0, uint32_t a1, uint32_t a2, uint32_t a3,
                                        uint32_t b0, uint32_t b1) {
    asm volatile("mma.sync.aligned.m16n8k32.row.col.f32.e4m3.e4m3.f32 "
                 "{%0,%1,%2,%3}, {%4,%5,%6,%7}, {%8,%9}, {%0,%1,%2,%3};"
                 : "+f"(c[0]), "+f"(c[1]), "+f"(c[2]), "+f"(c[3])
                 : "r"(a0), "r"(a1), "r"(a2), "r"(a3), "r"(b0), "r"(b1));
}

// ---------------------------------------------------------------------------
// Branchless sorted top-5 insert (ascending; static indices only)
// ---------------------------------------------------------------------------
#define INSERT5(sd, si, d, idx) do {                                          \
    if ((d) < sd[4]) {                                                        \
        bool c0 = (d) < sd[0], c1 = (d) < sd[1], c2 = (d) < sd[2], c3 = (d) < sd[3]; \
        sd[4] = c3 ? sd[3] : (d);          si[4] = c3 ? si[3] : (idx);        \
        sd[3] = c3 ? (c2 ? sd[2] : (d)) : sd[3]; si[3] = c3 ? (c2 ? si[2] : (idx)) : si[3]; \
        sd[2] = c2 ? (c1 ? sd[1] : (d)) : sd[2]; si[2] = c2 ? (c1 ? si[1] : (idx)) : si[2]; \
        sd[1] = c1 ? (c0 ? sd[0] : (d)) : sd[1]; si[1] = c1 ? (c0 ? si[0] : (idx)) : si[1]; \
        sd[0] = c0 ? (d) : sd[0];          si[0] = c0 ? (idx) : si[0];        \
    }                                                                         \
} while (0)

// slot-level min of the 8 distances owned by slot (mf, qa/qb)
#define SLOTMIN(mf, qa, qb)                                                   \
    fminf(fminf(fminf(acc[mf][0][qa], acc[mf][0][qb]),                        \
                fminf(acc[mf][1][qa], acc[mf][1][qb])),                       \
          fminf(fminf(acc[mf][2][qa], acc[mf][2][qb]),                        \
                fminf(acc[mf][3][qa], acc[mf][3][qb])))

// gated insert: enter the heavy body only if some element can enter top-5
#define SLOTINS(sd, si, mf, qa, qb) do {                                      \
    if (SLOTMIN(mf, qa, qb) < sd[4]) {                                        \
        _Pragma("unroll")                                                     \
        for (int nf_ = 0; nf_ < 4; nf_++) {                                   \
            int gg0 = colbase + ecol0 + nf_ * 8;                              \
            INSERT5(sd, si, acc[mf][nf_][qa], gg0);                           \
            INSERT5(sd, si, acc[mf][nf_][qb], gg0 + 1);                       \
        }                                                                     \
    }                                                                         \
} while (0)

// ---------------------------------------------------------------------------
// SMEM layout (bytes)
// ---------------------------------------------------------------------------
#define OFF_B        0                       // double buffer: +0 / +TILEB (53248)
#define OFF_A        (2 * TILEB)             // 53248, A: 128 rows x 208B = 26624
#define OFF_DUMPD    (OFF_A + TM * RSB)      // 79872  float [128][NDUMP] (40960)
#define OFF_DUMPI    (OFF_DUMPD + TM*NDUMP*4)// 120832 int   [128][NDUMP] (40960)
#define OFF_C16      (OFF_DUMPI + TM*NDUMP*4)// 161792 int   [128][16]    (8192)
#define OFF_MBAR     (OFF_C16 + TM*NCAND*4)  // 169984 two 8B mbarriers
#define SMEM_BYTES   (OFF_MBAR + 16)         // 170000

// ---------------------------------------------------------------------------
// Prep kernel: one warp per row index w (< NTRAIN)
// ---------------------------------------------------------------------------
__device__ __forceinline__ uint32_t pack4_e4m3(float f0, float f1, float f2, float f3) {
    uint32_t b0 = __nv_cvt_float_to_fp8(f0, __NV_SATFINITE, __NV_E4M3);
    uint32_t b1 = __nv_cvt_float_to_fp8(f1, __NV_SATFINITE, __NV_E4M3);
    uint32_t b2 = __nv_cvt_float_to_fp8(f2, __NV_SATFINITE, __NV_E4M3);
    uint32_t b3 = __nv_cvt_float_to_fp8(f3, __NV_SATFINITE, __NV_E4M3);
    return b0 | (b1 << 8) | (b2 << 16) | (b3 << 24);
}

__global__ void prep_kernel(const float* __restrict__ Htest,
                            const float* __restrict__ Htrain) {
    int w    = (blockIdx.x * blockDim.x + threadIdx.x) >> 5;
    int lane = threadIdx.x & 31;
    if (w >= NTRAIN) return;

    const float4* tr = (const float4*)(Htrain + (size_t)w * DIM);  // 48 float4
    const float4* te = (const float4*)(Htest  + (size_t)w * DIM);
    uint32_t* ob = (uint32_t*)(g_B8 + (size_t)(w >> 7) * TILEB + (size_t)(w & 127) * RSB);
    uint32_t* oa = (uint32_t*)(g_A8 + (size_t)w * DIM);

    float s = 0.f;
    #pragma unroll
    for (int j = 0; j < 2; j++) {
        int c = lane + 32 * j;
        if (c < 48) {
            float4 b = tr[c];
            float4 a = te[c];
            s = fmaf(b.x, b.x, s); s = fmaf(b.y, b.y, s);
            s = fmaf(b.z, b.z, s); s = fmaf(b.w, b.w, s);
            ob[c] = pack4_e4m3(b.x, b.y, b.z, b.w);
            oa[c] = pack4_e4m3(a.x, a.y, a.z, a.w);
        }
    }
    #pragma unroll
    for (int o = 16; o; o >>= 1) s += __shfl_xor_sync(0xffffffffu, s, o);
    if (lane == 0) g_ynorm[w] = s;
}

// ---------------------------------------------------------------------------
// Main kernel: fp8 mma.sync, gated private top-5 -> compact -> fp32 re-rank
// ---------------------------------------------------------------------------
__global__ __launch_bounds__(NTHREADS, 1)
void knn_mma_kernel(const float* __restrict__ Htest,
                    const float* __restrict__ Htrain,
                    const float* __restrict__ phat,
                    float* __restrict__ out) {
    extern __shared__ __align__(1024) char smem[];
    const uint32_t sbase = smem_u32(smem);
    const int tid   = threadIdx.x;
    const int wid   = tid >> 5;
    const int lid   = tid & 31;
    const int warpM = wid & 3;       // 0..3 -> rows warpM*32..+31
    const int warpN = wid >> 2;      // 0..3 -> cols warpN*32..+31
    const int m0    = blockIdx.x * TM;

    float* dumpd = (float*)(smem + OFF_DUMPD);
    int*   dumpi = (int*)  (smem + OFF_DUMPI);
    int*   c16   = (int*)  (smem + OFF_C16);
    const uint32_t mbar0 = sbase + OFF_MBAR;
    const uint32_t mbar1 = sbase + OFF_MBAR + 8;

    // ---- prologue ----
    if (tid == 0) { MBAR_INIT(mbar0, 1); MBAR_INIT(mbar1, 1); }
    FENCE_PROXY_ASYNC();
    __syncthreads();

    if (tid == 0) {
        MBAR_EXPECT_TX(mbar0, TILEB);
        CP_BULK(sbase + OFF_B, (const char*)g_B8, TILEB, mbar0);
    }

    // A tile: 128 rows x 12 chunks of 16B via cp.async (one-time)
    #pragma unroll
    for (int it = 0; it < (TM * 12) / NTHREADS; it++) {
        int g  = tid + it * NTHREADS;
        int r  = g / 12;
        int ch = g % 12;
        CP_ASYNC16(sbase + OFF_A + r * RSB + ch * 16,
                   (const char*)g_A8 + (size_t)(m0 + r) * DIM + ch * 16);
    }
    CP_COMMIT();
    CP_WAIT0();
    __syncthreads();

    const int lrow   = lid & 15;
    const int lchunk = lid >> 4;
    uint32_t a_addr[2];
    #pragma unroll
    for (int mf = 0; mf < 2; mf++)
        a_addr[mf] = sbase + OFF_A +
                     (warpM * 32 + mf * 16 + lrow) * RSB + lchunk * 16;

    const int ecol0 = warpN * 32 + 2 * (lid & 3);

    // ---- private selection: 4 row-slots, gated branchless top-5 each ----
    float sd0[NSLOT], sd1[NSLOT], sd2[NSLOT], sd3[NSLOT];
    int   si0[NSLOT], si1[NSLOT], si2[NSLOT], si3[NSLOT];
    #pragma unroll
    for (int i = 0; i < NSLOT; i++) {
        sd0[i] = FLT_MAX; sd1[i] = FLT_MAX; sd2[i] = FLT_MAX; sd3[i] = FLT_MAX;
        si0[i] = -1; si1[i] = -1; si2[i] = -1; si3[i] = -1;
    }

    // ---- main loop over B tiles: 1 barrier + 1 mbar-wait per tile ----
    for (int jt = 0; jt < NTILES; jt++) {
        const int cur = jt & 1;
        const int colbase = jt * TN;

        if (tid == 0 && jt + 1 < NTILES) {
            uint32_t mb = (1 - cur) ? mbar1 : mbar0;
            MBAR_EXPECT_TX(mb, TILEB);
            CP_BULK(sbase + OFF_B + (1 - cur) * TILEB,
                    (const char*)g_B8 + (size_t)(jt + 1) * TILEB, TILEB, mb);
        }

        // prefetch this tile's y-norms (independent of B data)
        float yv[8];
        #pragma unroll
        for (int nf = 0; nf < 4; nf++) {
            int g0 = colbase + ecol0 + nf * 8;
            yv[nf * 2]     = __ldg(&g_ynorm[g0]);
            yv[nf * 2 + 1] = __ldg(&g_ynorm[g0 + 1]);
        }

        MBAR_WAIT(cur ? mbar1 : mbar0, (jt >> 1) & 1);   // tile jt data ready

        // ---- 128x128x192 fp8 mma: warp tile 32x32 ----
        float acc[2][4][4];
        #pragma unroll
        for (int mf = 0; mf < 2; mf++)
            #pragma unroll
            for (int nf = 0; nf < 4; nf++)
                #pragma unroll
                for (int q = 0; q < 4; q++) acc[mf][nf][q] = 0.f;

        uint32_t b_base = sbase + OFF_B + cur * TILEB +
                          (warpN * 32 + lrow) * RSB + lchunk * 16;

        #pragma unroll
        for (int ks = 0; ks < KSTEPS; ks++) {
            const uint32_t ka = ks * 32;
            uint32_t a[2][4], b[2][4];
            LDMATRIX_X4(a[0][0], a[0][1], a[0][2], a[0][3], a_addr[0] + ka);
            LDMATRIX_X4(a[1][0], a[1][1], a[1][2], a[1][3], a_addr[1] + ka);
            LDMATRIX_X4(b[0][0], b[0][1], b[0][2], b[0][3], b_base + ka);
            LDMATRIX_X4(b[1][0], b[1][1], b[1][2], b[1][3],
                        b_base + 16 * RSB + ka);
            #pragma unroll
            for (int mf = 0; mf < 2; mf++)
                #pragma unroll
                for (int nf = 0; nf < 4; nf++)
                    mma_fp8(acc[mf][nf],
                            a[mf][0], a[mf][1], a[mf][2], a[mf][3],
                            b[nf >> 1][nf & 1], b[nf >> 1][2 + (nf & 1)]);
        }

        // ---- epilogue: acc -> distances in place, then gated inserts ----
        #pragma unroll
        for (int mf = 0; mf < 2; mf++)
            #pragma unroll
            for (int nf = 0; nf < 4; nf++) {
                acc[mf][nf][0] = fmaf(-2.f, acc[mf][nf][0], yv[nf * 2]);
                acc[mf][nf][1] = fmaf(-2.f, acc[mf][nf][1], yv[nf * 2 + 1]);
                acc[mf][nf][2] = fmaf(-2.f, acc[mf][nf][2], yv[nf * 2]);
                acc[mf][nf][3] = fmaf(-2.f, acc[mf][nf][3], yv[nf * 2 + 1]);
            }

        SLOTINS(sd0, si0, 0, 0, 1);
        SLOTINS(sd1, si1, 0, 2, 3);
        SLOTINS(sd2, si2, 1, 0, 1);
        SLOTINS(sd3, si3, 1, 2, 3);

        __syncthreads();   // all reads of buf[cur] done before jt+1 overwrite
    }

    // ---- dump: 16 owners x 5 candidates per row ----
    {
        const int owner = warpN * 4 + (lid & 3);           // 0..15
        const int rbase = warpM * 32 + (lid >> 2);
        #pragma unroll
        for (int i = 0; i < NSLOT; i++) {
            dumpd[(rbase +  0) * NDUMP + owner * NSLOT + i] = sd0[i];
            dumpi[(rbase +  0) * NDUMP + owner * NSLOT + i] = si0[i];
            dumpd[(rbase +  8) * NDUMP + owner * NSLOT + i] = sd1[i];
            dumpi[(rbase +  8) * NDUMP + owner * NSLOT + i] = si1[i];
            dumpd[(rbase + 16) * NDUMP + owner * NSLOT + i] = sd2[i];
            dumpi[(rbase + 16) * NDUMP + owner * NSLOT + i] = si2[i];
            dumpd[(rbase + 24) * NDUMP + owner * NSLOT + i] = sd3[i];
            dumpi[(rbase + 24) * NDUMP + owner * NSLOT + i] = si3[i];
        }
    }
    __syncthreads();

    // ---- compact: one thread per row selects top-16 of the 80 ----
    if (tid < TM) {
        float pd[NCAND]; int pi[NCAND];
        #pragma unroll
        for (int i = 0; i < NCAND; i++) { pd[i] = FLT_MAX; pi[i] = -1; }
        for (int i = 0; i < NDUMP; i++) {
            float d = dumpd[tid * NDUMP + i];
            if (d < pd[NCAND - 1]) {
                int idx = dumpi[tid * NDUMP + i];
                int j = NCAND - 1;
                while (j > 0 && pd[j - 1] > d) {
                    pd[j] = pd[j - 1]; pi[j] = pi[j - 1]; j--;
                }
                pd[j] = d; pi[j] = idx;
            }
        }
        #pragma unroll
        for (int i = 0; i < NCAND; i++) c16[tid * NCAND + i] = pi[i];
    }
    __syncthreads();

    // ---- exact fp32 re-rank: warp per row, 16 candidates ----
    for (int r = wid; r < TM; r += 16) {
        const int rowg = m0 + r;
        const float* xrow = Htest + (size_t)rowg * DIM;
        float xv[6];
        #pragma unroll
        for (int j = 0; j < 6; j++) xv[j] = xrow[lid + 32 * j];

        float bd[KNN]; int bi[KNN];
        #pragma unroll
        for (int i = 0; i < KNN; i++) { bd[i] = FLT_MAX; bi[i] = 0x7fffffff; }

        for (int c = 0; c < NCAND; c++) {
            int idx = c16[r * NCAND + c];
            if (idx < 0) continue;
            const float* trow = Htrain + (size_t)idx * DIM;
            float s = 0.f;
            #pragma unroll
            for (int j = 0; j < 6; j++) s = fmaf(xv[j], trow[lid + 32 * j], s);
            #pragma unroll
            for (int o = 16; o; o >>= 1) s += __shfl_xor_sync(0xffffffffu, s, o);
            if (lid == 0) {
                float d = g_ynorm[idx] - 2.0f * s;
                int j = KNN;
                while (j > 0 && (d < bd[j - 1] ||
                                 (d == bd[j - 1] && idx < bi[j - 1]))) j--;
                if (j < KNN) {
                    for (int q = KNN - 1; q > j; q--) { bd[q] = bd[q-1]; bi[q] = bi[q-1]; }
                    bd[j] = d; bi[j] = idx;
                }
            }
        }
        if (lid == 0) {
            float s0 = 0.f, s1 = 0.f;
            #pragma unroll
            for (int i = 0; i < KNN; i++) {
                int idx = bi[i];
                s0 += phat[idx];
                s1 += phat[NTRAIN + idx];
            }
            out[rowg]         = s0 * (1.0f / KNN);
            out[NTEST + rowg] = s1 * (1.0f / KNN);
        }
    }
}

// ---------------------------------------------------------------------------
extern "C" void kernel_launch(void* const* d_in, const int* in_sizes, int n_in,
                              void* d_out, int out_size) {
    const float* Htest  = (const float*)d_in[0];
    const float* Htrain = (const float*)d_in[1];
    const float* phat   = (const float*)d_in[2];
    float* out = (float*)d_out;

    prep_kernel<<<(NTRAIN * 32) / 256, 256>>>(Htest, Htrain);

    cudaFuncSetAttribute(knn_mma_kernel,
                         cudaFuncAttributeMaxDynamicSharedMemorySize, SMEM_BYTES);
    knn_mma_kernel<<<NTEST / TM, NTHREADS, SMEM_BYTES>>>(Htest, Htrain, phat, out);
}

// round 16
// speedup vs baseline: 1.0745x; 1.0745x over previous
#include <cuda_runtime.h>
#include <cuda_bf16.h>
#include <cuda_fp8.h>
#include <cfloat>
#include <cstdint>

// ---------------------------------------------------------------------------
// Problem constants
// ---------------------------------------------------------------------------
#define NTEST   16384
#define NTRAIN  16384
#define DIM     192
#define NCLASS  2
#define KNN     5

#define TM      128                 // test rows per CTA
#define TN      128                 // train cols per tile
#define NTILES  (NTRAIN / TN)       // 128
#define KSTEPS  (DIM / 32)          // 6 mma k-steps (fp8: K=32 per step)
#define NTHREADS 512                // 16 warps: 4 (M) x 4 (N), warp tile 32x32
#define NSLOT   5                   // private top-5 per (thread,row-slot)
#define NOWN    16                  // owners per row
#define NDUMP   (NOWN * NSLOT)      // 80 candidates dumped per row
#define NCAND   16                  // compacted top-16 per row for re-rank

#define RSB     208                 // bytes per fp8 row in smem (192 + 16 pad)
#define TILEB   (TN * RSB)          // 26624 bytes per B tile
#define IDXMASK 0x3FFFu             // low 14 bits hold train index

// ---------------------------------------------------------------------------
// Global scratch (no cudaMalloc allowed)
// ---------------------------------------------------------------------------
__device__ float   g_ynorm[NTRAIN];
__device__ uint8_t g_A8[NTEST * DIM];            // H_test  e4m3, row-major 192B rows
__device__ uint8_t g_B8[NTILES * TILEB];         // H_train e4m3, tile-padded layout

// ---------------------------------------------------------------------------
// PTX helpers (base ISA: sm_89/sm_90 features, legal on sm_100 without 'a')
// ---------------------------------------------------------------------------
__device__ __forceinline__ uint32_t smem_u32(const void* p) {
    uint32_t a;
    asm("{ .reg .u64 t; cvta.to.shared.u64 t, %1; cvt.u32.u64 %0, t; }"
        : "=r"(a) : "l"(p));
    return a;
}

#define CP_ASYNC16(dst, src) \
    asm volatile("cp.async.cg.shared.global [%0], [%1], 16;" :: "r"(dst), "l"(src))
#define CP_COMMIT() asm volatile("cp.async.commit_group;" ::: "memory")
#define CP_WAIT0()  asm volatile("cp.async.wait_group 0;" ::: "memory")

#define MBAR_INIT(mb, n) \
    asm volatile("mbarrier.init.shared.b64 [%0], %1;" :: "r"((uint32_t)(mb)), "r"((uint32_t)(n)) : "memory")
#define MBAR_EXPECT_TX(mb, bytes) \
    asm volatile("mbarrier.arrive.expect_tx.shared.b64 _, [%0], %1;" :: "r"((uint32_t)(mb)), "r"((uint32_t)(bytes)) : "memory")
#define CP_BULK(dst, src, sz, mb) \
    asm volatile("cp.async.bulk.shared::cluster.global.mbarrier::complete_tx::bytes [%0], [%1], %2, [%3];" \
                 :: "r"((uint32_t)(dst)), "l"(src), "r"((uint32_t)(sz)), "r"((uint32_t)(mb)) : "memory")
#define FENCE_PROXY_ASYNC() asm volatile("fence.proxy.async.shared::cta;" ::: "memory")

#define MBAR_WAIT(mb, par) do {                                                     \
    uint32_t _mb = (uint32_t)(mb); uint32_t _p = (uint32_t)(par); uint32_t _done;   \
    asm volatile("{ .reg .pred p; mbarrier.try_wait.parity.acquire.cta.shared::cta.b64 p, [%1], %2; selp.b32 %0, 1, 0, p; }" \
                 : "=r"(_done) : "r"(_mb), "r"(_p) : "memory");                     \
    if (!_done) {                                                                   \
        asm volatile("{ .reg .pred P1; WL_%=: mbarrier.try_wait.parity.acquire.cta.shared::cta.b64 P1, [%0], %1, 0x989680; @P1 bra.uni WD_%=; bra.uni WL_%=; WD_%=: }" \
                     :: "r"(_mb), "r"(_p) : "memory");                              \
    }                                                                               \
} while (0)

#define LDMATRIX_X4(r0, r1, r2, r3, addr) \
    asm volatile("ldmatrix.sync.aligned.m8n8.x4.shared.b16 {%0,%1,%2,%3}, [%4];" \
                 : "=r"(r0), "=r"(r1), "=r"(r2), "=r"(r3) : "r"(addr))

__device__ __forceinline__ void mma_fp8(float* c,
                                        uint32_t a0, uint32_t a1, uint32_t a2, uint32_t a3,
                                        uint32_t b0, uint32_t b1) {
    asm volatile("mma.sync.aligned.m16n8k32.row.col.f32.e4m3.e4m3.f32 "
                 "{%0,%1,%2,%3}, {%4,%5,%6,%7}, {%8,%9}, {%0,%1,%2,%3};"
                 : "+f"(c[0]), "+f"(c[1]), "+f"(c[2]), "+f"(c[3])
                 : "r"(a0), "r"(a1), "r"(a2), "r"(a3), "r"(b0), "r"(b1));
}

// ---------------------------------------------------------------------------
// Packed-key top-5: sorted ascending scalars s0..s4.
// key = (quantized dist, 18 bits, resolution 1/128) << 14 | train index.
// Gated 10-op unsigned min/max bubble; no index SELs, no dynamic indexing.
// ---------------------------------------------------------------------------
#define INSK(S, k) do {                                                       \
    uint32_t _k = (k);                                                        \
    if (_k < S##4) {                                                          \
        uint32_t _t;                                                          \
        _t = min(S##0, _k); _k = max(S##0, _k); S##0 = _t;                    \
        _t = min(S##1, _k); _k = max(S##1, _k); S##1 = _t;                    \
        _t = min(S##2, _k); _k = max(S##2, _k); S##2 = _t;                    \
        _t = min(S##3, _k); _k = max(S##3, _k); S##3 = _t;                    \
        S##4 = min(S##4, _k);                                                 \
    }                                                                         \
} while (0)

__device__ __forceinline__ uint32_t packkey(float d, int idx) {
    uint32_t q = (uint32_t)(fmaxf(d, 0.0f) * 128.0f);   // 1/128 resolution
    q = min(q, 0x3FFFFu);                               // clamp to 18 bits
    return (q << 14) | (uint32_t)idx;
}

// ---------------------------------------------------------------------------
// SMEM layout (bytes)
// ---------------------------------------------------------------------------
#define OFF_B        0                       // double buffer: +0 / +TILEB (53248)
#define OFF_A        (2 * TILEB)             // 53248, A: 128 rows x 208B = 26624
#define OFF_DUMPK    (OFF_A + TM * RSB)      // 79872  u32 [128][NDUMP] (40960)
#define OFF_C16      (OFF_DUMPK + TM*NDUMP*4)// 120832 int [128][16]    (8192)
#define OFF_MBAR     (OFF_C16 + TM*NCAND*4)  // 129024 two 8B mbarriers
#define SMEM_BYTES   (OFF_MBAR + 16)         // 129040

// ---------------------------------------------------------------------------
// Prep kernel: one warp per row index w (< NTRAIN)
// ---------------------------------------------------------------------------
__device__ __forceinline__ uint32_t pack4_e4m3(float f0, float f1, float f2, float f3) {
    uint32_t b0 = __nv_cvt_float_to_fp8(f0, __NV_SATFINITE, __NV_E4M3);
    uint32_t b1 = __nv_cvt_float_to_fp8(f1, __NV_SATFINITE, __NV_E4M3);
    uint32_t b2 = __nv_cvt_float_to_fp8(f2, __NV_SATFINITE, __NV_E4M3);
    uint32_t b3 = __nv_cvt_float_to_fp8(f3, __NV_SATFINITE, __NV_E4M3);
    return b0 | (b1 << 8) | (b2 << 16) | (b3 << 24);
}

__global__ void prep_kernel(const float* __restrict__ Htest,
                            const float* __restrict__ Htrain) {
    int w    = (blockIdx.x * blockDim.x + threadIdx.x) >> 5;
    int lane = threadIdx.x & 31;
    if (w >= NTRAIN) return;

    const float4* tr = (const float4*)(Htrain + (size_t)w * DIM);  // 48 float4
    const float4* te = (const float4*)(Htest  + (size_t)w * DIM);
    uint32_t* ob = (uint32_t*)(g_B8 + (size_t)(w >> 7) * TILEB + (size_t)(w & 127) * RSB);
    uint32_t* oa = (uint32_t*)(g_A8 + (size_t)w * DIM);

    float s = 0.f;
    #pragma unroll
    for (int j = 0; j < 2; j++) {
        int c = lane + 32 * j;
        if (c < 48) {
            float4 b = tr[c];
            float4 a = te[c];
            s = fmaf(b.x, b.x, s); s = fmaf(b.y, b.y, s);
            s = fmaf(b.z, b.z, s); s = fmaf(b.w, b.w, s);
            ob[c] = pack4_e4m3(b.x, b.y, b.z, b.w);
            oa[c] = pack4_e4m3(a.x, a.y, a.z, a.w);
        }
    }
    #pragma unroll
    for (int o = 16; o; o >>= 1) s += __shfl_xor_sync(0xffffffffu, s, o);
    if (lane == 0) g_ynorm[w] = s;
}

// ---------------------------------------------------------------------------
// Main kernel: pipelined fp8 mma.sync, packed-key top-5 -> compact -> re-rank
// ---------------------------------------------------------------------------
__global__ __launch_bounds__(NTHREADS, 1)
void knn_mma_kernel(const float* __restrict__ Htest,
                    const float* __restrict__ Htrain,
                    const float* __restrict__ phat,
                    float* __restrict__ out) {
    extern __shared__ __align__(1024) char smem[];
    const uint32_t sbase = smem_u32(smem);
    const int tid   = threadIdx.x;
    const int wid   = tid >> 5;
    const int lid   = tid & 31;
    const int warpM = wid & 3;       // 0..3 -> rows warpM*32..+31
    const int warpN = wid >> 2;      // 0..3 -> cols warpN*32..+31
    const int m0    = blockIdx.x * TM;

    uint32_t* dumpk = (uint32_t*)(smem + OFF_DUMPK);
    int*      c16   = (int*)     (smem + OFF_C16);
    const uint32_t mbar0 = sbase + OFF_MBAR;
    const uint32_t mbar1 = sbase + OFF_MBAR + 8;

    // ---- prologue ----
    if (tid == 0) { MBAR_INIT(mbar0, 1); MBAR_INIT(mbar1, 1); }
    FENCE_PROXY_ASYNC();
    __syncthreads();

    if (tid == 0) {
        MBAR_EXPECT_TX(mbar0, TILEB);
        CP_BULK(sbase + OFF_B, (const char*)g_B8, TILEB, mbar0);
    }

    // A tile: 128 rows x 12 chunks of 16B via cp.async (one-time)
    #pragma unroll
    for (int it = 0; it < (TM * 12) / NTHREADS; it++) {
        int g  = tid + it * NTHREADS;
        int r  = g / 12;
        int ch = g % 12;
        CP_ASYNC16(sbase + OFF_A + r * RSB + ch * 16,
                   (const char*)g_A8 + (size_t)(m0 + r) * DIM + ch * 16);
    }
    CP_COMMIT();
    CP_WAIT0();
    __syncthreads();

    const int lrow   = lid & 15;
    const int lchunk = lid >> 4;
    uint32_t a_addr[2];
    #pragma unroll
    for (int mf = 0; mf < 2; mf++)
        a_addr[mf] = sbase + OFF_A +
                     (warpM * 32 + mf * 16 + lrow) * RSB + lchunk * 16;

    const int ecol0 = warpN * 32 + 2 * (lid & 3);

    // ---- private packed-key top-5 per row-slot (20 scalar registers) ----
    uint32_t k00 = ~0u, k01 = ~0u, k02 = ~0u, k03 = ~0u, k04 = ~0u;  // slot0
    uint32_t k10 = ~0u, k11 = ~0u, k12 = ~0u, k13 = ~0u, k14 = ~0u;  // slot1
    uint32_t k20 = ~0u, k21 = ~0u, k22 = ~0u, k23 = ~0u, k24 = ~0u;  // slot2
    uint32_t k30 = ~0u, k31 = ~0u, k32 = ~0u, k33 = ~0u, k34 = ~0u;  // slot3

    // ---- main loop over B tiles: 1 barrier + 1 mbar-wait per tile ----
    for (int jt = 0; jt < NTILES; jt++) {
        const int cur = jt & 1;
        const int colbase = jt * TN;

        if (tid == 0 && jt + 1 < NTILES) {
            uint32_t mb = (1 - cur) ? mbar1 : mbar0;
            MBAR_EXPECT_TX(mb, TILEB);
            CP_BULK(sbase + OFF_B + (1 - cur) * TILEB,
                    (const char*)g_B8 + (size_t)(jt + 1) * TILEB, TILEB, mb);
        }

        MBAR_WAIT(cur ? mbar1 : mbar0, (jt >> 1) & 1);   // tile jt data ready

        // ---- 128x128x192 fp8 mma, software-pipelined over ksteps ----
        float acc[2][4][4];
        #pragma unroll
        for (int mf = 0; mf < 2; mf++)
            #pragma unroll
            for (int nf = 0; nf < 4; nf++)
                #pragma unroll
                for (int q = 0; q < 4; q++) acc[mf][nf][q] = 0.f;

        uint32_t b_base = sbase + OFF_B + cur * TILEB +
                          (warpN * 32 + lrow) * RSB + lchunk * 16;

        uint32_t aF[2][2][4], bF[2][2][4];   // [stage][mf or bhalf][frag]

        // preload kstep 0 into stage 0
        LDMATRIX_X4(aF[0][0][0], aF[0][0][1], aF[0][0][2], aF[0][0][3], a_addr[0]);
        LDMATRIX_X4(aF[0][1][0], aF[0][1][1], aF[0][1][2], aF[0][1][3], a_addr[1]);
        LDMATRIX_X4(bF[0][0][0], bF[0][0][1], bF[0][0][2], bF[0][0][3], b_base);
        LDMATRIX_X4(bF[0][1][0], bF[0][1][1], bF[0][1][2], bF[0][1][3],
                    b_base + 16 * RSB);

        #pragma unroll
        for (int ks = 0; ks < KSTEPS; ks++) {
            const int st  = ks & 1;
            const int nst = st ^ 1;
            if (ks + 1 < KSTEPS) {
                const uint32_t ka = (ks + 1) * 32;
                LDMATRIX_X4(aF[nst][0][0], aF[nst][0][1], aF[nst][0][2], aF[nst][0][3],
                            a_addr[0] + ka);
                LDMATRIX_X4(aF[nst][1][0], aF[nst][1][1], aF[nst][1][2], aF[nst][1][3],
                            a_addr[1] + ka);
                LDMATRIX_X4(bF[nst][0][0], bF[nst][0][1], bF[nst][0][2], bF[nst][0][3],
                            b_base + ka);
                LDMATRIX_X4(bF[nst][1][0], bF[nst][1][1], bF[nst][1][2], bF[nst][1][3],
                            b_base + 16 * RSB + ka);
            }
            #pragma unroll
            for (int mf = 0; mf < 2; mf++)
                #pragma unroll
                for (int nf = 0; nf < 4; nf++)
                    mma_fp8(acc[mf][nf],
                            aF[st][mf][0], aF[st][mf][1], aF[st][mf][2], aF[st][mf][3],
                            bF[st][nf >> 1][nf & 1], bF[st][nf >> 1][2 + (nf & 1)]);
        }

        // ---- epilogue: dist -> int-scaled packed key -> gated bubble insert ----
        #pragma unroll
        for (int nf = 0; nf < 4; nf++) {
            const int g0 = colbase + ecol0 + nf * 8;
            const int g1 = g0 + 1;
            const float y0 = __ldg(&g_ynorm[g0]);
            const float y1 = __ldg(&g_ynorm[g1]);
            {   // mf = 0 -> slots 0 (row+0) and 1 (row+8)
                const float* cc = acc[0][nf];
                uint32_t q00 = packkey(fmaf(-2.f, cc[0], y0), g0);
                uint32_t q01 = packkey(fmaf(-2.f, cc[1], y1), g1);
                uint32_t q10 = packkey(fmaf(-2.f, cc[2], y0), g0);
                uint32_t q11 = packkey(fmaf(-2.f, cc[3], y1), g1);
                INSK(k0, q00); INSK(k0, q01);
                INSK(k1, q10); INSK(k1, q11);
            }
            {   // mf = 1 -> slots 2 and 3
                const float* cc = acc[1][nf];
                uint32_t q00 = packkey(fmaf(-2.f, cc[0], y0), g0);
                uint32_t q01 = packkey(fmaf(-2.f, cc[1], y1), g1);
                uint32_t q10 = packkey(fmaf(-2.f, cc[2], y0), g0);
                uint32_t q11 = packkey(fmaf(-2.f, cc[3], y1), g1);
                INSK(k2, q00); INSK(k2, q01);
                INSK(k3, q10); INSK(k3, q11);
            }
        }

        __syncthreads();   // all reads of buf[cur] done before jt+1 overwrite
    }

    // ---- dump: 16 owners x 5 keys per row ----
    {
        const int owner = warpN * 4 + (lid & 3);           // 0..15
        const int rbase = warpM * 32 + (lid >> 2);
        uint32_t* d0 = dumpk + (rbase +  0) * NDUMP + owner * NSLOT;
        uint32_t* d1 = dumpk + (rbase +  8) * NDUMP + owner * NSLOT;
        uint32_t* d2 = dumpk + (rbase + 16) * NDUMP + owner * NSLOT;
        uint32_t* d3 = dumpk + (rbase + 24) * NDUMP + owner * NSLOT;
        d0[0]=k00; d0[1]=k01; d0[2]=k02; d0[3]=k03; d0[4]=k04;
        d1[0]=k10; d1[1]=k11; d1[2]=k12; d1[3]=k13; d1[4]=k14;
        d2[0]=k20; d2[1]=k21; d2[2]=k22; d2[3]=k23; d2[4]=k24;
        d3[0]=k30; d3[1]=k31; d3[2]=k32; d3[3]=k33; d3[4]=k34;
    }
    __syncthreads();

    // ---- compact: one thread per row selects 16 smallest keys of the 80 ----
    if (tid < TM) {
        uint32_t pk[NCAND];
        #pragma unroll
        for (int i = 0; i < NCAND; i++) pk[i] = ~0u;
        for (int i = 0; i < NDUMP; i++) {
            uint32_t k = dumpk[tid * NDUMP + i];
            if (k < pk[NCAND - 1]) {
                int j = NCAND - 1;
                while (j > 0 && pk[j - 1] > k) { pk[j] = pk[j - 1]; j--; }
                pk[j] = k;
            }
        }
        #pragma unroll
        for (int i = 0; i < NCAND; i++)
            c16[tid * NCAND + i] = (pk[i] == ~0u) ? -1 : (int)(pk[i] & IDXMASK);
    }
    __syncthreads();

    // ---- exact fp32 re-rank: warp per row, 16 candidates ----
    for (int r = wid; r < TM; r += 16) {
        const int rowg = m0 + r;
        const float* xrow = Htest + (size_t)rowg * DIM;
        float xv[6];
        #pragma unroll
        for (int j = 0; j < 6; j++) xv[j] = xrow[lid + 32 * j];

        float bd[KNN]; int bi[KNN];
        #pragma unroll
        for (int i = 0; i < KNN; i++) { bd[i] = FLT_MAX; bi[i] = 0x7fffffff; }

        for (int c = 0; c < NCAND; c++) {
            int idx = c16[r * NCAND + c];
            if (idx < 0) continue;
            const float* trow = Htrain + (size_t)idx * DIM;
            float s = 0.f;
            #pragma unroll
            for (int j = 0; j < 6; j++) s = fmaf(xv[j], trow[lid + 32 * j], s);
            #pragma unroll
            for (int o = 16; o; o >>= 1) s += __shfl_xor_sync(0xffffffffu, s, o);
            if (lid == 0) {
                float d = g_ynorm[idx] - 2.0f * s;
                int j = KNN;
                while (j > 0 && (d < bd[j - 1] ||
                                 (d == bd[j - 1] && idx < bi[j - 1]))) j--;
                if (j < KNN) {
                    for (int q = KNN - 1; q > j; q--) { bd[q] = bd[q-1]; bi[q] = bi[q-1]; }
                    bd[j] = d; bi[j] = idx;
                }
            }
        }
        if (lid == 0) {
            float s0 = 0.f, s1 = 0.f;
            #pragma unroll
            for (int i = 0; i < KNN; i++) {
                int idx = bi[i];
                s0 += phat[idx];
                s1 += phat[NTRAIN + idx];
            }
            out[rowg]         = s0 * (1.0f / KNN);
            out[NTEST + rowg] = s1 * (1.0f / KNN);
        }
    }
}

// ---------------------------------------------------------------------------
extern "C" void kernel_launch(void* const* d_in, const int* in_sizes, int n_in,
                              void* d_out, int out_size) {
    const float* Htest  = (const float*)d_in[0];
    const float* Htrain = (const float*)d_in[1];
    const float* phat   = (const float*)d_in[2];
    float* out = (float*)d_out;

    prep_kernel<<<(NTRAIN * 32) / 256, 256>>>(Htest, Htrain);

    cudaFuncSetAttribute(knn_mma_kernel,
                         cudaFuncAttributeMaxDynamicSharedMemorySize, SMEM_BYTES);
    knn_mma_kernel<<<NTEST / TM, NTHREADS, SMEM_BYTES>>>(Htest, Htrain, phat, out);
}

// round 17
// speedup vs baseline: 1.1319x; 1.0534x over previous
#include <cuda_runtime.h>
#include <cuda_bf16.h>
#include <cuda_fp8.h>
#include <cfloat>
#include <cstdint>

// ---------------------------------------------------------------------------
// Problem constants
// ---------------------------------------------------------------------------
#define NTEST   16384
#define NTRAIN  16384
#define DIM     192
#define NCLASS  2
#define KNN     5

#define TM      128                 // test rows per CTA
#define TN      128                 // train cols per tile
#define NTILES  (NTRAIN / TN)       // 128
#define KSTEPS  (DIM / 32)          // 6 mma k-steps (fp8: K=32 per step)
#define NTHREADS 512                // 16 warps: 4 (M) x 4 (N), warp tile 32x32
#define NSLOT   5                   // private top-5 per (thread,row-slot)
#define NOWN    16                  // owners per row
#define NDUMP   (NOWN * NSLOT)      // 80 candidates dumped per row
#define NCAND   16                  // compacted top-16 per row for re-rank

#define RSB     208                 // bytes per fp8 row in smem (192 + 16 pad)
#define TILEB   (TN * RSB)          // 26624 bytes per B tile
#define IDXMASK 0x3FFFu             // low 14 bits hold train index

// ---------------------------------------------------------------------------
// Global scratch (no cudaMalloc allowed)
// ---------------------------------------------------------------------------
__device__ float   g_ynorm[NTRAIN];
__device__ uint8_t g_A8[NTEST * DIM];            // H_test  e4m3, row-major 192B rows
__device__ uint8_t g_B8[NTILES * TILEB];         // H_train e4m3, tile-padded layout

// ---------------------------------------------------------------------------
// PTX helpers (base ISA: sm_89/sm_90 features, legal on sm_100 without 'a')
// ---------------------------------------------------------------------------
__device__ __forceinline__ uint32_t smem_u32(const void* p) {
    uint32_t a;
    asm("{ .reg .u64 t; cvta.to.shared.u64 t, %1; cvt.u32.u64 %0, t; }"
        : "=r"(a) : "l"(p));
    return a;
}

#define CP_ASYNC16(dst, src) \
    asm volatile("cp.async.cg.shared.global [%0], [%1], 16;" :: "r"(dst), "l"(src))
#define CP_COMMIT() asm volatile("cp.async.commit_group;" ::: "memory")
#define CP_WAIT0()  asm volatile("cp.async.wait_group 0;" ::: "memory")

#define MBAR_INIT(mb, n) \
    asm volatile("mbarrier.init.shared.b64 [%0], %1;" :: "r"((uint32_t)(mb)), "r"((uint32_t)(n)) : "memory")
#define MBAR_EXPECT_TX(mb, bytes) \
    asm volatile("mbarrier.arrive.expect_tx.shared.b64 _, [%0], %1;" :: "r"((uint32_t)(mb)), "r"((uint32_t)(bytes)) : "memory")
#define CP_BULK(dst, src, sz, mb) \
    asm volatile("cp.async.bulk.shared::cluster.global.mbarrier::complete_tx::bytes [%0], [%1], %2, [%3];" \
                 :: "r"((uint32_t)(dst)), "l"(src), "r"((uint32_t)(sz)), "r"((uint32_t)(mb)) : "memory")
#define FENCE_PROXY_ASYNC() asm volatile("fence.proxy.async.shared::cta;" ::: "memory")

#define MBAR_WAIT(mb, par) do {                                                     \
    uint32_t _mb = (uint32_t)(mb); uint32_t _p = (uint32_t)(par); uint32_t _done;   \
    asm volatile("{ .reg .pred p; mbarrier.try_wait.parity.acquire.cta.shared::cta.b64 p, [%1], %2; selp.b32 %0, 1, 0, p; }" \
                 : "=r"(_done) : "r"(_mb), "r"(_p) : "memory");                     \
    if (!_done) {                                                                   \
        asm volatile("{ .reg .pred P1; WL_%=: mbarrier.try_wait.parity.acquire.cta.shared::cta.b64 P1, [%0], %1, 0x989680; @P1 bra.uni WD_%=; bra.uni WL_%=; WD_%=: }" \
                     :: "r"(_mb), "r"(_p) : "memory");                              \
    }                                                                               \
} while (0)

#define LDMATRIX_X4(r0, r1, r2, r3, addr) \
    asm volatile("ldmatrix.sync.aligned.m8n8.x4.shared.b16 {%0,%1,%2,%3}, [%4];" \
                 : "=r"(r0), "=r"(r1), "=r"(r2), "=r"(r3) : "r"(addr))

__device__ __forceinline__ void mma_fp8(float* c,
                                        uint32_t a0, uint32_t a1, uint32_t a2, uint32_t a3,
                                        uint32_t b0, uint32_t b1) {
    asm volatile("mma.sync.aligned.m16n8k32.row.col.f32.e4m3.e4m3.f32 "
                 "{%0,%1,%2,%3}, {%4,%5,%6,%7}, {%8,%9}, {%0,%1,%2,%3};"
                 : "+f"(c[0]), "+f"(c[1]), "+f"(c[2]), "+f"(c[3])
                 : "r"(a0), "r"(a1), "r"(a2), "r"(a3), "r"(b0), "r"(b1));
}

// first-kstep variant: C = 0 constant regs (no per-tile acc zeroing needed)
__device__ __forceinline__ void mma_fp8_z(float* c,
                                          uint32_t a0, uint32_t a1, uint32_t a2, uint32_t a3,
                                          uint32_t b0, uint32_t b1) {
    asm volatile("mma.sync.aligned.m16n8k32.row.col.f32.e4m3.e4m3.f32 "
                 "{%0,%1,%2,%3}, {%4,%5,%6,%7}, {%8,%9}, {%10,%11,%12,%13};"
                 : "=f"(c[0]), "=f"(c[1]), "=f"(c[2]), "=f"(c[3])
                 : "r"(a0), "r"(a1), "r"(a2), "r"(a3), "r"(b0), "r"(b1),
                   "f"(0.f), "f"(0.f), "f"(0.f), "f"(0.f));
}

// ---------------------------------------------------------------------------
// Packed-key top-5: sorted ascending scalars s0..s4.
// key = (u32)(d*128 + 2048) << 14 | idx   (monotone in d; offset kills the
// negative-distance corner so no fmax/clamp is needed; max key << 2^32).
// Gated 10-op unsigned min/max bubble; no index SELs, no dynamic indexing.
// ---------------------------------------------------------------------------
#define INSK(S, k) do {                                                       \
    uint32_t _k = (k);                                                        \
    if (_k < S##4) {                                                          \
        uint32_t _t;                                                          \
        _t = min(S##0, _k); _k = max(S##0, _k); S##0 = _t;                    \
        _t = min(S##1, _k); _k = max(S##1, _k); S##1 = _t;                    \
        _t = min(S##2, _k); _k = max(S##2, _k); S##2 = _t;                    \
        _t = min(S##3, _k); _k = max(S##3, _k); S##3 = _t;                    \
        S##4 = min(S##4, _k);                                                 \
    }                                                                         \
} while (0)

// key from accumulated dot + precomputed y128 = y*128 + 2048: 3 ops total
#define MAKEKEY(dot, y128v, col) \
    (((uint32_t)fmaf((dot), -256.0f, (y128v))) * 16384u + (uint32_t)(col))

// ---------------------------------------------------------------------------
// SMEM layout (bytes)
// ---------------------------------------------------------------------------
#define OFF_B        0                       // double buffer: +0 / +TILEB (53248)
#define OFF_A        (2 * TILEB)             // 53248, A: 128 rows x 208B = 26624
#define OFF_DUMPK    (OFF_A + TM * RSB)      // 79872  u32 [128][NDUMP] (40960)
#define OFF_C16      (OFF_DUMPK + TM*NDUMP*4)// 120832 int [128][16]    (8192)
#define OFF_MBAR     (OFF_C16 + TM*NCAND*4)  // 129024 two 8B mbarriers
#define SMEM_BYTES   (OFF_MBAR + 16)         // 129040

// ---------------------------------------------------------------------------
// Prep kernel: one warp per row index w (< NTRAIN)
// ---------------------------------------------------------------------------
__device__ __forceinline__ uint32_t pack4_e4m3(float f0, float f1, float f2, float f3) {
    uint32_t b0 = __nv_cvt_float_to_fp8(f0, __NV_SATFINITE, __NV_E4M3);
    uint32_t b1 = __nv_cvt_float_to_fp8(f1, __NV_SATFINITE, __NV_E4M3);
    uint32_t b2 = __nv_cvt_float_to_fp8(f2, __NV_SATFINITE, __NV_E4M3);
    uint32_t b3 = __nv_cvt_float_to_fp8(f3, __NV_SATFINITE, __NV_E4M3);
    return b0 | (b1 << 8) | (b2 << 16) | (b3 << 24);
}

__global__ void prep_kernel(const float* __restrict__ Htest,
                            const float* __restrict__ Htrain) {
    int w    = (blockIdx.x * blockDim.x + threadIdx.x) >> 5;
    int lane = threadIdx.x & 31;
    if (w >= NTRAIN) return;

    const float4* tr = (const float4*)(Htrain + (size_t)w * DIM);  // 48 float4
    const float4* te = (const float4*)(Htest  + (size_t)w * DIM);
    uint32_t* ob = (uint32_t*)(g_B8 + (size_t)(w >> 7) * TILEB + (size_t)(w & 127) * RSB);
    uint32_t* oa = (uint32_t*)(g_A8 + (size_t)w * DIM);

    float s = 0.f;
    #pragma unroll
    for (int j = 0; j < 2; j++) {
        int c = lane + 32 * j;
        if (c < 48) {
            float4 b = tr[c];
            float4 a = te[c];
            s = fmaf(b.x, b.x, s); s = fmaf(b.y, b.y, s);
            s = fmaf(b.z, b.z, s); s = fmaf(b.w, b.w, s);
            ob[c] = pack4_e4m3(b.x, b.y, b.z, b.w);
            oa[c] = pack4_e4m3(a.x, a.y, a.z, a.w);
        }
    }
    #pragma unroll
    for (int o = 16; o; o >>= 1) s += __shfl_xor_sync(0xffffffffu, s, o);
    if (lane == 0) g_ynorm[w] = s;
}

// ---------------------------------------------------------------------------
// Main kernel: pipelined fp8 mma.sync, packed-key top-5 -> compact -> re-rank
// ---------------------------------------------------------------------------
__global__ __launch_bounds__(NTHREADS, 1)
void knn_mma_kernel(const float* __restrict__ Htest,
                    const float* __restrict__ Htrain,
                    const float* __restrict__ phat,
                    float* __restrict__ out) {
    extern __shared__ __align__(1024) char smem[];
    const uint32_t sbase = smem_u32(smem);
    const int tid   = threadIdx.x;
    const int wid   = tid >> 5;
    const int lid   = tid & 31;
    const int warpM = wid & 3;       // 0..3 -> rows warpM*32..+31
    const int warpN = wid >> 2;      // 0..3 -> cols warpN*32..+31
    const int m0    = blockIdx.x * TM;

    uint32_t* dumpk = (uint32_t*)(smem + OFF_DUMPK);
    int*      c16   = (int*)     (smem + OFF_C16);
    const uint32_t mbar0 = sbase + OFF_MBAR;
    const uint32_t mbar1 = sbase + OFF_MBAR + 8;

    // ---- prologue ----
    if (tid == 0) { MBAR_INIT(mbar0, 1); MBAR_INIT(mbar1, 1); }
    FENCE_PROXY_ASYNC();
    __syncthreads();

    if (tid == 0) {
        MBAR_EXPECT_TX(mbar0, TILEB);
        CP_BULK(sbase + OFF_B, (const char*)g_B8, TILEB, mbar0);
    }

    // A tile: 128 rows x 12 chunks of 16B via cp.async (one-time)
    #pragma unroll
    for (int it = 0; it < (TM * 12) / NTHREADS; it++) {
        int g  = tid + it * NTHREADS;
        int r  = g / 12;
        int ch = g % 12;
        CP_ASYNC16(sbase + OFF_A + r * RSB + ch * 16,
                   (const char*)g_A8 + (size_t)(m0 + r) * DIM + ch * 16);
    }
    CP_COMMIT();
    CP_WAIT0();
    __syncthreads();

    const int lrow   = lid & 15;
    const int lchunk = lid >> 4;
    uint32_t a_addr[2];
    #pragma unroll
    for (int mf = 0; mf < 2; mf++)
        a_addr[mf] = sbase + OFF_A +
                     (warpM * 32 + mf * 16 + lrow) * RSB + lchunk * 16;

    const int ecol0 = warpN * 32 + 2 * (lid & 3);

    // ---- private packed-key top-5 per row-slot (20 scalar registers) ----
    uint32_t k00 = ~0u, k01 = ~0u, k02 = ~0u, k03 = ~0u, k04 = ~0u;  // slot0
    uint32_t k10 = ~0u, k11 = ~0u, k12 = ~0u, k13 = ~0u, k14 = ~0u;  // slot1
    uint32_t k20 = ~0u, k21 = ~0u, k22 = ~0u, k23 = ~0u, k24 = ~0u;  // slot2
    uint32_t k30 = ~0u, k31 = ~0u, k32 = ~0u, k33 = ~0u, k34 = ~0u;  // slot3

    // ---- main loop over B tiles: 1 barrier + 1 mbar-wait per tile ----
    for (int jt = 0; jt < NTILES; jt++) {
        const int cur = jt & 1;
        const int colbase = jt * TN;

        if (tid == 0 && jt + 1 < NTILES) {
            uint32_t mb = (1 - cur) ? mbar1 : mbar0;
            MBAR_EXPECT_TX(mb, TILEB);
            CP_BULK(sbase + OFF_B + (1 - cur) * TILEB,
                    (const char*)g_B8 + (size_t)(jt + 1) * TILEB, TILEB, mb);
        }

        // prefetch + prescale this tile's y-norms (independent of B data)
        float y128v[8];
        #pragma unroll
        for (int nf = 0; nf < 4; nf++) {
            int g0 = colbase + ecol0 + nf * 8;
            y128v[nf * 2]     = fmaf(__ldg(&g_ynorm[g0]),     128.0f, 2048.0f);
            y128v[nf * 2 + 1] = fmaf(__ldg(&g_ynorm[g0 + 1]), 128.0f, 2048.0f);
        }

        MBAR_WAIT(cur ? mbar1 : mbar0, (jt >> 1) & 1);   // tile jt data ready

        // ---- 128x128x192 fp8 mma, software-pipelined over ksteps ----
        float acc[2][4][4];

        uint32_t b_base = sbase + OFF_B + cur * TILEB +
                          (warpN * 32 + lrow) * RSB + lchunk * 16;

        uint32_t aF[2][2][4], bF[2][2][4];   // [stage][mf or bhalf][frag]

        // preload kstep 0 into stage 0
        LDMATRIX_X4(aF[0][0][0], aF[0][0][1], aF[0][0][2], aF[0][0][3], a_addr[0]);
        LDMATRIX_X4(aF[0][1][0], aF[0][1][1], aF[0][1][2], aF[0][1][3], a_addr[1]);
        LDMATRIX_X4(bF[0][0][0], bF[0][0][1], bF[0][0][2], bF[0][0][3], b_base);
        LDMATRIX_X4(bF[0][1][0], bF[0][1][1], bF[0][1][2], bF[0][1][3],
                    b_base + 16 * RSB);

        #pragma unroll
        for (int ks = 0; ks < KSTEPS; ks++) {
            const int st  = ks & 1;
            const int nst = st ^ 1;
            if (ks + 1 < KSTEPS) {
                const uint32_t ka = (ks + 1) * 32;
                LDMATRIX_X4(aF[nst][0][0], aF[nst][0][1], aF[nst][0][2], aF[nst][0][3],
                            a_addr[0] + ka);
                LDMATRIX_X4(aF[nst][1][0], aF[nst][1][1], aF[nst][1][2], aF[nst][1][3],
                            a_addr[1] + ka);
                LDMATRIX_X4(bF[nst][0][0], bF[nst][0][1], bF[nst][0][2], bF[nst][0][3],
                            b_base + ka);
                LDMATRIX_X4(bF[nst][1][0], bF[nst][1][1], bF[nst][1][2], bF[nst][1][3],
                            b_base + 16 * RSB + ka);
            }
            #pragma unroll
            for (int mf = 0; mf < 2; mf++)
                #pragma unroll
                for (int nf = 0; nf < 4; nf++) {
                    if (ks == 0)
                        mma_fp8_z(acc[mf][nf],
                                  aF[st][mf][0], aF[st][mf][1], aF[st][mf][2], aF[st][mf][3],
                                  bF[st][nf >> 1][nf & 1], bF[st][nf >> 1][2 + (nf & 1)]);
                    else
                        mma_fp8(acc[mf][nf],
                                aF[st][mf][0], aF[st][mf][1], aF[st][mf][2], aF[st][mf][3],
                                bF[st][nf >> 1][nf & 1], bF[st][nf >> 1][2 + (nf & 1)]);
                }
        }

        // ---- epilogue: 3-op keys -> gated 10-op bubble insert ----
        #pragma unroll
        for (int nf = 0; nf < 4; nf++) {
            const int g0 = colbase + ecol0 + nf * 8;
            const int g1 = g0 + 1;
            const float y0 = y128v[nf * 2];
            const float y1 = y128v[nf * 2 + 1];
            {   // mf = 0 -> slots 0 (row+0) and 1 (row+8)
                const float* cc = acc[0][nf];
                uint32_t q00 = MAKEKEY(cc[0], y0, g0);
                uint32_t q01 = MAKEKEY(cc[1], y1, g1);
                uint32_t q10 = MAKEKEY(cc[2], y0, g0);
                uint32_t q11 = MAKEKEY(cc[3], y1, g1);
                INSK(k0, q00); INSK(k0, q01);
                INSK(k1, q10); INSK(k1, q11);
            }
            {   // mf = 1 -> slots 2 and 3
                const float* cc = acc[1][nf];
                uint32_t q00 = MAKEKEY(cc[0], y0, g0);
                uint32_t q01 = MAKEKEY(cc[1], y1, g1);
                uint32_t q10 = MAKEKEY(cc[2], y0, g0);
                uint32_t q11 = MAKEKEY(cc[3], y1, g1);
                INSK(k2, q00); INSK(k2, q01);
                INSK(k3, q10); INSK(k3, q11);
            }
        }

        __syncthreads();   // all reads of buf[cur] done before jt+1 overwrite
    }

    // ---- dump: 16 owners x 5 keys per row ----
    {
        const int owner = warpN * 4 + (lid & 3);           // 0..15
        const int rbase = warpM * 32 + (lid >> 2);
        uint32_t* d0 = dumpk + (rbase +  0) * NDUMP + owner * NSLOT;
        uint32_t* d1 = dumpk + (rbase +  8) * NDUMP + owner * NSLOT;
        uint32_t* d2 = dumpk + (rbase + 16) * NDUMP + owner * NSLOT;
        uint32_t* d3 = dumpk + (rbase + 24) * NDUMP + owner * NSLOT;
        d0[0]=k00; d0[1]=k01; d0[2]=k02; d0[3]=k03; d0[4]=k04;
        d1[0]=k10; d1[1]=k11; d1[2]=k12; d1[3]=k13; d1[4]=k14;
        d2[0]=k20; d2[1]=k21; d2[2]=k22; d2[3]=k23; d2[4]=k24;
        d3[0]=k30; d3[1]=k31; d3[2]=k32; d3[3]=k33; d3[4]=k34;
    }
    __syncthreads();

    // ---- compact: one thread per row selects 16 smallest keys of the 80 ----
    if (tid < TM) {
        uint32_t pk[NCAND];
        #pragma unroll
        for (int i = 0; i < NCAND; i++) pk[i] = ~0u;
        for (int i = 0; i < NDUMP; i++) {
            uint32_t k = dumpk[tid * NDUMP + i];
            if (k < pk[NCAND - 1]) {
                int j = NCAND - 1;
                while (j > 0 && pk[j - 1] > k) { pk[j] = pk[j - 1]; j--; }
                pk[j] = k;
            }
        }
        #pragma unroll
        for (int i = 0; i < NCAND; i++)
            c16[tid * NCAND + i] = (pk[i] == ~0u) ? -1 : (int)(pk[i] & IDXMASK);
    }
    __syncthreads();

    // ---- exact fp32 re-rank: warp per row, 16 candidates ----
    for (int r = wid; r < TM; r += 16) {
        const int rowg = m0 + r;
        const float* xrow = Htest + (size_t)rowg * DIM;
        float xv[6];
        #pragma unroll
        for (int j = 0; j < 6; j++) xv[j] = xrow[lid + 32 * j];

        float bd[KNN]; int bi[KNN];
        #pragma unroll
        for (int i = 0; i < KNN; i++) { bd[i] = FLT_MAX; bi[i] = 0x7fffffff; }

        for (int c = 0; c < NCAND; c++) {
            int idx = c16[r * NCAND + c];
            if (idx < 0) continue;
            const float* trow = Htrain + (size_t)idx * DIM;
            float s = 0.f;
            #pragma unroll
            for (int j = 0; j < 6; j++) s = fmaf(xv[j], trow[lid + 32 * j], s);
            #pragma unroll
            for (int o = 16; o; o >>= 1) s += __shfl_xor_sync(0xffffffffu, s, o);
            if (lid == 0) {
                float d = g_ynorm[idx] - 2.0f * s;
                int j = KNN;
                while (j > 0 && (d < bd[j - 1] ||
                                 (d == bd[j - 1] && idx < bi[j - 1]))) j--;
                if (j < KNN) {
                    for (int q = KNN - 1; q > j; q--) { bd[q] = bd[q-1]; bi[q] = bi[q-1]; }
                    bd[j] = d; bi[j] = idx;
                }
            }
        }
        if (lid == 0) {
            float s0 = 0.f, s1 = 0.f;
            #pragma unroll
            for (int i = 0; i < KNN; i++) {
                int idx = bi[i];
                s0 += phat[idx];
                s1 += phat[NTRAIN + idx];
            }
            out[rowg]         = s0 * (1.0f / KNN);
            out[NTEST + rowg] = s1 * (1.0f / KNN);
        }
    }
}

// ---------------------------------------------------------------------------
extern "C" void kernel_launch(void* const* d_in, const int* in_sizes, int n_in,
                              void* d_out, int out_size) {
    const float* Htest  = (const float*)d_in[0];
    const float* Htrain = (const float*)d_in[1];
    const float* phat   = (const float*)d_in[2];
    float* out = (float*)d_out;

    prep_kernel<<<(NTRAIN * 32) / 256, 256>>>(Htest, Htrain);

    cudaFuncSetAttribute(knn_mma_kernel,
                         cudaFuncAttributeMaxDynamicSharedMemorySize, SMEM_BYTES);
    knn_mma_kernel<<<NTEST / TM, NTHREADS, SMEM_BYTES>>>(Htest, Htrain, phat, out);
}